// round 15
// baseline (speedup 1.0000x reference)
#include <cuda_runtime.h>
#include <cuda_fp16.h>
#include <cstdint>

#define M_DIM 4096
#define K_DIM 4096
#define N_DIM 12288

// GEMM tiling: BN=192 (2048 tiles), BK=64, fused int4-B dequant
constexpr int BM = 128, BN = 192, BK = 64;
constexpr int KT = K_DIM / BK;                 // 64 k-tiles per output tile
constexpr int NTILES = (M_DIM / BM) * (N_DIM / BN);   // 2048
constexpr int NST = 8;                         // pipeline stages
constexpr int A_TILE = BM * BK * 2;            // 16384 B (fp16, swizzled)
constexpr int B_ROW = BN * 8;                  // 1536 B: one t-row of int2 (16 k-nibbles/n)
constexpr int B_RAW = 4 * B_ROW;               // 6144 B: 4 t-rows = 64 k
constexpr int SCL_BYTES = BN * 4;              // 768 B: fp32 scale per n
constexpr int STAGE_BYTES = A_TILE + B_RAW + SCL_BYTES;   // 23296
constexpr int SMEM_OFF = 1024;
constexpr int SMEM_BYTES = SMEM_OFF + NST * STAGE_BYTES;  // 187392

// A pack only (B is consumed raw from the input tensor)
__device__ __half g_Apack[(size_t)M_DIM * K_DIM];   // tiles (mb*64+kt): 128x64, swz c^(r&7)

// ---------------------------------------------------------------------------
// Pack A: fp32 [M,K] -> fp16 swizzled 128x64 tiles
// ---------------------------------------------------------------------------
__global__ void convA_kernel(const float* __restrict__ A) {
    int id = blockIdx.x * 256 + threadIdx.x;    // M*512 16B-chunk ids
    int m = id >> 9;
    int ch = id & 511;
    int kt = ch >> 3, c = ch & 7;
    const float4* src = reinterpret_cast<const float4*>(
        A + (size_t)m * K_DIM + kt * 64 + c * 8);
    float4 v0 = src[0], v1 = src[1];
    __half2 h[4];
    h[0] = __floats2half2_rn(v0.x, v0.y);
    h[1] = __floats2half2_rn(v0.z, v0.w);
    h[2] = __floats2half2_rn(v1.x, v1.y);
    h[3] = __floats2half2_rn(v1.z, v1.w);
    int mb = m >> 7, r = m & 127;
    int cs = c ^ (r & 7);
    char* dst = (char*)g_Apack + (size_t)(mb * 64 + kt) * A_TILE + r * 128 + cs * 16;
    *reinterpret_cast<uint4*>(dst) = *reinterpret_cast<uint4*>(h);
}

// ---------------------------------------------------------------------------
// helpers
// ---------------------------------------------------------------------------
__device__ __forceinline__ uint32_t smem_u32(const void* p) {
    return (uint32_t)__cvta_generic_to_shared(p);
}
__device__ __forceinline__ void mbar_init(uint32_t a, uint32_t cnt) {
    asm volatile("mbarrier.init.shared.b64 [%0], %1;" :: "r"(a), "r"(cnt) : "memory");
}
__device__ __forceinline__ void mbar_expect_tx(uint32_t a, uint32_t bytes) {
    asm volatile("mbarrier.arrive.expect_tx.shared.b64 _, [%0], %1;"
                 :: "r"(a), "r"(bytes) : "memory");
}
__device__ __forceinline__ void mbar_arrive(uint32_t a) {
    asm volatile("mbarrier.arrive.shared.b64 _, [%0];" :: "r"(a) : "memory");
}
__device__ __forceinline__ void mbar_wait(uint32_t a, uint32_t parity) {
    asm volatile(
        "{\n\t.reg .pred P;\n"
        "W0_%=:\n\t"
        "mbarrier.try_wait.parity.acquire.cta.shared::cta.b64 P, [%0], %1, 0x989680;\n\t"
        "@P bra.uni W1_%=;\n\t"
        "bra.uni W0_%=;\n\t"
        "W1_%=:\n\t}"
        :: "r"(a), "r"(parity) : "memory");
}
__device__ __forceinline__ void bulk_g2s(uint32_t dst, const void* src,
                                         uint32_t bytes, uint32_t mbar) {
    asm volatile(
        "cp.async.bulk.shared::cluster.global.mbarrier::complete_tx::bytes "
        "[%0], [%1], %2, [%3];"
        :: "r"(dst), "l"(src), "r"(bytes), "r"(mbar) : "memory");
}
__device__ __forceinline__ void ldsm4(uint32_t* r, uint32_t addr) {
    asm volatile("ldmatrix.sync.aligned.m8n8.x4.shared.b16 {%0,%1,%2,%3}, [%4];"
                 : "=r"(r[0]), "=r"(r[1]), "=r"(r[2]), "=r"(r[3]) : "r"(addr));
}
__device__ __forceinline__ void mma16816(float* c, const uint32_t* a, const uint32_t* b) {
    asm volatile("mma.sync.aligned.m16n8k16.row.col.f32.f16.f16.f32 "
                 "{%0,%1,%2,%3}, {%4,%5,%6,%7}, {%8,%9}, {%0,%1,%2,%3};"
                 : "+f"(c[0]), "+f"(c[1]), "+f"(c[2]), "+f"(c[3])
                 : "r"(a[0]), "r"(a[1]), "r"(a[2]), "r"(a[3]),
                   "r"(b[0]), "r"(b[1]));
}

// int4 byte -> scaled half2. w: packed int32 (8 nibbles), sh = (lane&3)*8.
// Extract byte, splat nibbles into half lanes at exponent 1024 (0x6400 magic),
// subtract 1032 exactly (= q-8), multiply by per-n scale (half2).
__device__ __forceinline__ uint32_t dq(uint32_t w, uint32_t sh, uint32_t scu) {
    uint32_t x = w >> sh;
    uint32_t v = (x & 0xFu) | ((x << 12) & 0x000F0000u) | 0x64006400u;
    const uint32_t c1032 = 0x64086408u;
    __half2 hv = __hsub2(*reinterpret_cast<__half2*>(&v),
                         *reinterpret_cast<const __half2*>(&c1032));
    hv = __hmul2(hv, *reinterpret_cast<__half2*>(&scu));
    return *reinterpret_cast<uint32_t*>(&hv);
}

// ---------------------------------------------------------------------------
// Persistent fused GEMM. 256 threads = 8 warps (64x48 warp tiles). Stage holds
// A fp16 (swizzled) + raw int4 B rows + fp32 scales. B fragments are built in
// registers (LDS broadcast + magic-number convert), no B ldmatrix/smem pack.
// full[st]: tx barrier (1). empty[st]: 8 warp arrivals. Distributed refill.
// ---------------------------------------------------------------------------
__global__ __launch_bounds__(256, 1)
void gemm_hmma_kernel(const int* __restrict__ Bq, const float* __restrict__ s,
                      const float* __restrict__ bias, float* __restrict__ C) {
    extern __shared__ char smem[];
    uint32_t sb = smem_u32(smem);
    int tid = threadIdx.x, wid = tid >> 5, lane = tid & 31;
    int p = blockIdx.x, P = gridDim.x;

    if (tid == 0) {
#pragma unroll
        for (int st = 0; st < NST; st++) {
            mbar_init(sb + st * 8, 1);            // full[st]
            mbar_init(sb + 64 + st * 8, 8);       // empty[st]
        }
    }
    __syncthreads();

    int ntiles = (NTILES - p + P - 1) / P;
    int GI = ntiles * KT;

    // fill global iteration f's stage: A tile + 4 raw B rows + scale row
    auto fill = [&](int f) {
        int st = f & (NST - 1);
        if (f >= NST) mbar_wait(sb + 64 + st * 8, ((f >> 3) - 1) & 1);
        int tile = p + (f >> 6) * P;
        int ktf = f & 63;
        int mbf = tile & 31, nbf = tile >> 5;
        uint32_t fb = sb + st * 8;
        mbar_expect_tx(fb, STAGE_BYTES);
        uint32_t sdst = sb + SMEM_OFF + st * STAGE_BYTES;
        bulk_g2s(sdst, (const char*)g_Apack + (size_t)(mbf * 64 + ktf) * A_TILE,
                 A_TILE, fb);
        const char* bsrc = (const char*)Bq +
            ((size_t)(ktf * 4) * N_DIM + (size_t)nbf * BN) * 8;
#pragma unroll
        for (int t_l = 0; t_l < 4; t_l++)
            bulk_g2s(sdst + A_TILE + t_l * B_ROW,
                     bsrc + (size_t)t_l * N_DIM * 8, B_ROW, fb);
        const char* ssrc = (const char*)s +
            ((size_t)(ktf >> 1) * N_DIM + (size_t)nbf * BN) * 4;
        bulk_g2s(sdst + A_TILE + B_RAW, ssrc, SCL_BYTES, fb);
    };
    if (tid == 0) {
        for (int f = 0; f < NST && f < GI; f++) fill(f);
    }

    // geometry: warp tile 64x48; A via ldmatrix, B via register dequant
    int g = lane >> 3, tr = lane & 7;
    int m_warp = (wid & 1) * 64;
    int n_warp = (wid >> 1) * 48;
    int aRow0 = m_warp + (g & 1) * 8 + tr;
    int aH = g >> 1;
    int ln4 = lane >> 2;                 // n-offset within 8
    uint32_t sh = (lane & 3) * 8;        // byte select within packed int32

    for (int tile_i = 0; tile_i < ntiles; tile_i++) {
        int tile = p + tile_i * P;
        int mb = tile & 31, nb = tile >> 5;

        float acc[4][6][4];
#pragma unroll
        for (int i = 0; i < 4; i++)
#pragma unroll
            for (int j = 0; j < 6; j++)
#pragma unroll
                for (int k = 0; k < 4; k++) acc[i][j][k] = 0.f;

        for (int kt = 0; kt < KT; kt++) {
            int gi = tile_i * KT + kt;
            int st = gi & (NST - 1);
            mbar_wait(sb + st * 8, (gi >> 3) & 1);
            char* stage = smem + SMEM_OFF + st * STAGE_BYTES;
            uint32_t As = sb + SMEM_OFF + st * STAGE_BYTES;

            // per-tile scales (constant over this kt: group=128 covers 64 k)
            const float* scl = reinterpret_cast<const float*>(stage + A_TILE + B_RAW);
            uint32_t scu[3][2];
#pragma unroll
            for (int nt2 = 0; nt2 < 3; nt2++)
#pragma unroll
                for (int h = 0; h < 2; h++) {
                    __half hf = __float2half_rn(
                        scl[n_warp + nt2 * 16 + h * 8 + ln4]);
                    __half2 h2 = __half2half2(hf);
                    scu[nt2][h] = *reinterpret_cast<uint32_t*>(&h2);
                }

#pragma unroll
            for (int ks = 0; ks < 4; ks++) {
                int kc = 2 * ks;
                uint32_t a0[4][4];
#pragma unroll
                for (int mt = 0; mt < 4; mt++) {
                    int r = aRow0 + mt * 16;
                    int c = (kc + aH) ^ (r & 7);
                    ldsm4(a0[mt], As + r * 128 + c * 16);
                }
                const int2* prow = reinterpret_cast<const int2*>(
                    stage + A_TILE + ks * B_ROW);
#pragma unroll
                for (int nt2 = 0; nt2 < 3; nt2++) {
                    int o0 = n_warp + nt2 * 16 + ln4;
                    int2 P0 = prow[o0];
                    int2 P1 = prow[o0 + 8];
                    if (ks == 3 && nt2 == 2 && lane == 0)
                        mbar_arrive(sb + 64 + st * 8);   // all stage reads issued
                    uint32_t q[4];
                    q[0] = dq(P0.x, sh, scu[nt2][0]);
                    q[1] = dq(P0.y, sh, scu[nt2][0]);
                    q[2] = dq(P1.x, sh, scu[nt2][1]);
                    q[3] = dq(P1.y, sh, scu[nt2][1]);
#pragma unroll
                    for (int mt = 0; mt < 4; mt++) {
                        mma16816(acc[mt][nt2 * 2], a0[mt], q);
                        mma16816(acc[mt][nt2 * 2 + 1], a0[mt], q + 2);
                    }
                }
            }

            // distributed refill: rotating warp issues next stage's loads
            if ((gi & 7) == wid && lane == 0) {
                int f = gi + NST;
                if (f < GI) fill(f);
            }
        }

        // epilogue: registers -> gmem (+bias); stage smem untouched
        int m0 = mb * BM + m_warp;
        int n0 = nb * BN + n_warp;
        float2 bv[6];
#pragma unroll
        for (int nt = 0; nt < 6; nt++)
            bv[nt] = *reinterpret_cast<const float2*>(
                &bias[n0 + nt * 8 + (lane & 3) * 2]);
#pragma unroll
        for (int mt = 0; mt < 4; mt++) {
#pragma unroll
            for (int nt = 0; nt < 6; nt++) {
                int row = m0 + mt * 16 + (lane >> 2);
                int col = n0 + nt * 8 + (lane & 3) * 2;
                float2 v0 = make_float2(acc[mt][nt][0] + bv[nt].x,
                                        acc[mt][nt][1] + bv[nt].y);
                float2 v1 = make_float2(acc[mt][nt][2] + bv[nt].x,
                                        acc[mt][nt][3] + bv[nt].y);
                *reinterpret_cast<float2*>(&C[(size_t)row * N_DIM + col]) = v0;
                *reinterpret_cast<float2*>(&C[(size_t)(row + 8) * N_DIM + col]) = v1;
            }
        }
    }
}

// ---------------------------------------------------------------------------
// Launch
// ---------------------------------------------------------------------------
extern "C" void kernel_launch(void* const* d_in, const int* in_sizes, int n_in,
                              void* d_out, int out_size) {
    const float* A    = (const float*)d_in[0];
    const int*   B    = (const int*)  d_in[1];
    const float* s    = (const float*)d_in[2];
    const float* bias = (const float*)d_in[3];
    float* C = (float*)d_out;

    cudaFuncSetAttribute(gemm_hmma_kernel,
                         cudaFuncAttributeMaxDynamicSharedMemorySize, SMEM_BYTES);

    int nsm = 148;
    cudaDeviceGetAttribute(&nsm, cudaDevAttrMultiProcessorCount, 0);

    convA_kernel<<<(M_DIM * 512) / 256, 256>>>(A);
    gemm_hmma_kernel<<<nsm, 256, SMEM_BYTES>>>(B, s, bias, C);
}

// round 16
// speedup vs baseline: 1.3895x; 1.3895x over previous
#include <cuda_runtime.h>
#include <cuda_fp16.h>
#include <cstdint>

#define M_DIM 4096
#define K_DIM 4096
#define N_DIM 12288

// GEMM tiling: BN=96 -> 4096 tiles; 4096/152 = 26.95 (tail quantization ~1.5us)
constexpr int BM = 128, BN = 96, BK = 64;
constexpr int KT = K_DIM / BK;                 // 64 k-tiles per output tile
constexpr int NTILES = (M_DIM / BM) * (N_DIM / BN);   // 32 * 128 = 4096
constexpr int NST = 4;                         // pipeline stages
constexpr int A_TILE = BM * BK * 2;            // 16384 B
constexpr int B_TILE = BN * BK * 2;            // 12288 B
constexpr int STAGE_BYTES = A_TILE + B_TILE;   // 28672
constexpr int SMEM_OFF = 1024;
constexpr int SMEM_BYTES = SMEM_OFF + NST * STAGE_BYTES;   // 115712

// tile-packed, pre-swizzled operand blobs (128B rows, chunk swz c ^ (r&7))
__device__ __half g_Apack[(size_t)M_DIM * K_DIM];   // tiles (mb*64+kt): 128x64
__device__ __half g_Bpack[(size_t)N_DIM * K_DIM];   // tiles (nb*64+kt): 96x64 [n][k]

// ---------------------------------------------------------------------------
// Pack A: fp32 [M,K] -> fp16 swizzled 128x64 tiles
// ---------------------------------------------------------------------------
__global__ void convA_kernel(const float* __restrict__ A) {
    int id = blockIdx.x * 256 + threadIdx.x;    // M*512 16B-chunk ids
    int m = id >> 9;
    int ch = id & 511;
    int kt = ch >> 3, c = ch & 7;
    const float4* src = reinterpret_cast<const float4*>(
        A + (size_t)m * K_DIM + kt * 64 + c * 8);
    float4 v0 = src[0], v1 = src[1];
    __half2 h[4];
    h[0] = __floats2half2_rn(v0.x, v0.y);
    h[1] = __floats2half2_rn(v0.z, v0.w);
    h[2] = __floats2half2_rn(v1.x, v1.y);
    h[3] = __floats2half2_rn(v1.z, v1.w);
    int mb = m >> 7, r = m & 127;
    int cs = c ^ (r & 7);
    char* dst = (char*)g_Apack + (size_t)(mb * 64 + kt) * A_TILE + r * 128 + cs * 16;
    *reinterpret_cast<uint4*>(dst) = *reinterpret_cast<uint4*>(h);
}

// ---------------------------------------------------------------------------
// Dequant+pack W (smem-staged, coalesced): one block per (nb, kt) 96x64 tile.
// Thread o_l dequants the full 64-k row of n = nb*96+o_l into a swizzled
// smem tile; block then streams the tile to gmem with linear 16B stores.
// ---------------------------------------------------------------------------
__global__ __launch_bounds__(96, 8)
void dequant_kernel(const int* __restrict__ B, const float* __restrict__ s) {
    __shared__ char tile_s[B_TILE];
    int nb = blockIdx.x;            // 0..127
    int kt = blockIdx.y;            // 0..63
    int o_l = threadIdx.x;          // 0..95
    int o = nb * BN + o_l;
    int xm = o_l & 7;
#pragma unroll
    for (int tt = 0; tt < 4; tt++) {
        int t = kt * 4 + tt;
        int2 p = reinterpret_cast<const int2*>(B)[(size_t)t * N_DIM + o];
        float sc = s[(t >> 3) * N_DIM + o];
        __half2 h[8];
#pragma unroll
        for (int c8 = 0; c8 < 2; c8++) {
            int v = c8 ? p.y : p.x;
#pragma unroll
            for (int j = 0; j < 4; j++) {
                float w0 = (float)(((v >> (8 * j)) & 0xF) - 8) * sc;
                float w1 = (float)(((v >> (8 * j + 4)) & 0xF) - 8) * sc;
                h[c8 * 4 + j] = __floats2half2_rn(w0, w1);
            }
        }
        int c0 = tt * 2;
        *reinterpret_cast<uint4*>(tile_s + o_l * 128 + ((c0 ^ xm) * 16)) =
            *reinterpret_cast<uint4*>(h);
        *reinterpret_cast<uint4*>(tile_s + o_l * 128 + (((c0 + 1) ^ xm) * 16)) =
            *reinterpret_cast<uint4*>(h + 4);
    }
    __syncthreads();
    uint4* dst = reinterpret_cast<uint4*>(
        (char*)g_Bpack + (size_t)(nb * 64 + kt) * B_TILE);
    const uint4* srcp = reinterpret_cast<const uint4*>(tile_s);
#pragma unroll
    for (int i = 0; i < B_TILE / 16 / 96; i++)
        dst[i * 96 + threadIdx.x] = srcp[i * 96 + threadIdx.x];
}

// ---------------------------------------------------------------------------
// helpers
// ---------------------------------------------------------------------------
__device__ __forceinline__ uint32_t smem_u32(const void* p) {
    return (uint32_t)__cvta_generic_to_shared(p);
}
__device__ __forceinline__ void mbar_init(uint32_t a, uint32_t cnt) {
    asm volatile("mbarrier.init.shared.b64 [%0], %1;" :: "r"(a), "r"(cnt) : "memory");
}
__device__ __forceinline__ void mbar_expect_tx(uint32_t a, uint32_t bytes) {
    asm volatile("mbarrier.arrive.expect_tx.shared.b64 _, [%0], %1;"
                 :: "r"(a), "r"(bytes) : "memory");
}
__device__ __forceinline__ void mbar_arrive(uint32_t a) {
    asm volatile("mbarrier.arrive.shared.b64 _, [%0];" :: "r"(a) : "memory");
}
__device__ __forceinline__ void mbar_wait(uint32_t a, uint32_t parity) {
    asm volatile(
        "{\n\t.reg .pred P;\n"
        "W0_%=:\n\t"
        "mbarrier.try_wait.parity.acquire.cta.shared::cta.b64 P, [%0], %1, 0x989680;\n\t"
        "@P bra.uni W1_%=;\n\t"
        "bra.uni W0_%=;\n\t"
        "W1_%=:\n\t}"
        :: "r"(a), "r"(parity) : "memory");
}
__device__ __forceinline__ void bulk_g2s(uint32_t dst, const void* src,
                                         uint32_t bytes, uint32_t mbar) {
    asm volatile(
        "cp.async.bulk.shared::cluster.global.mbarrier::complete_tx::bytes "
        "[%0], [%1], %2, [%3];"
        :: "r"(dst), "l"(src), "r"(bytes), "r"(mbar) : "memory");
}
__device__ __forceinline__ void ldsm4(uint32_t* r, uint32_t addr) {
    asm volatile("ldmatrix.sync.aligned.m8n8.x4.shared.b16 {%0,%1,%2,%3}, [%4];"
                 : "=r"(r[0]), "=r"(r[1]), "=r"(r[2]), "=r"(r[3]) : "r"(addr));
}
__device__ __forceinline__ void mma16816(float* c, const uint32_t* a, const uint32_t* b) {
    asm volatile("mma.sync.aligned.m16n8k16.row.col.f32.f16.f16.f32 "
                 "{%0,%1,%2,%3}, {%4,%5,%6,%7}, {%8,%9}, {%0,%1,%2,%3};"
                 : "+f"(c[0]), "+f"(c[1]), "+f"(c[2]), "+f"(c[3])
                 : "r"(a[0]), "r"(a[1]), "r"(a[2]), "r"(a[3]),
                   "r"(b[0]), "r"(b[1]));
}

// ---------------------------------------------------------------------------
// Persistent GEMM. 256 threads = 8 compute warps (32x48). Distributed fill
// (rotating warp), fine-grain LDSM/MMA interleave, single-buffered frags.
// full[st]: tx barrier (1). empty[st]: 8 warp arrivals.
// ---------------------------------------------------------------------------
__global__ __launch_bounds__(256, 1)
void gemm_hmma_kernel(const float* __restrict__ bias, float* __restrict__ C) {
    extern __shared__ char smem[];
    uint32_t sb = smem_u32(smem);
    int tid = threadIdx.x, wid = tid >> 5, lane = tid & 31;
    int p = blockIdx.x, P = gridDim.x;

    if (tid == 0) {
#pragma unroll
        for (int st = 0; st < NST; st++) {
            mbar_init(sb + st * 8, 1);            // full[st]
            mbar_init(sb + 64 + st * 8, 8);       // empty[st]
        }
    }
    __syncthreads();

    int ntiles = (NTILES - p + P - 1) / P;
    int GI = ntiles * KT;

    // fill global iteration f's stage
    auto fill = [&](int f) {
        int st = f & (NST - 1);
        if (f >= NST) mbar_wait(sb + 64 + st * 8, ((f >> 2) - 1) & 1);
        int tile = p + (f >> 6) * P;
        int ktf = f & 63;
        int mbf = tile & 31, nbf = tile >> 5;
        uint32_t fb = sb + st * 8;
        mbar_expect_tx(fb, STAGE_BYTES);
        uint32_t sdst = sb + SMEM_OFF + st * STAGE_BYTES;
        bulk_g2s(sdst, (const char*)g_Apack + (size_t)(mbf * 64 + ktf) * A_TILE,
                 A_TILE, fb);
        bulk_g2s(sdst + A_TILE,
                 (const char*)g_Bpack + (size_t)(nbf * 64 + ktf) * B_TILE,
                 B_TILE, fb);
    };
    if (tid == 0) {
        for (int f = 0; f < NST && f < GI; f++) fill(f);
    }

    // per-thread ldmatrix geometry (warp tile 32x48, 128B smem rows)
    int g = lane >> 3, tr = lane & 7;
    int m_warp = (wid & 3) * 32;
    int n_warp = (wid >> 2) * 48;
    int aRow0 = m_warp + (g & 1) * 8 + tr;
    int aH = g >> 1;
    int bRow0 = n_warp + (g >> 1) * 8 + tr;
    int bH = g & 1;

    for (int tile_i = 0; tile_i < ntiles; tile_i++) {
        int tile = p + tile_i * P;
        int mb = tile & 31, nb = tile >> 5;

        float acc[2][6][4];
#pragma unroll
        for (int i = 0; i < 2; i++)
#pragma unroll
            for (int j = 0; j < 6; j++)
#pragma unroll
                for (int k = 0; k < 4; k++) acc[i][j][k] = 0.f;

        for (int kt = 0; kt < KT; kt++) {
            int gi = tile_i * KT + kt;
            int st = gi & (NST - 1);
            mbar_wait(sb + st * 8, (gi >> 2) & 1);
            uint32_t As = sb + SMEM_OFF + st * STAGE_BYTES;
            uint32_t Bs = As + A_TILE;

#pragma unroll
            for (int ks = 0; ks < 4; ks++) {
                int kc = 2 * ks;
                uint32_t a0[2][4];
#pragma unroll
                for (int mt = 0; mt < 2; mt++) {
                    int r = aRow0 + mt * 16;
                    int c = (kc + aH) ^ (r & 7);
                    ldsm4(a0[mt], As + r * 128 + c * 16);
                }
                // interleave: one B ldsm, then its 4 MMAs
#pragma unroll
                for (int nt2 = 0; nt2 < 3; nt2++) {
                    int r = bRow0 + nt2 * 16;
                    int c = (kc + bH) ^ (r & 7);
                    uint32_t q[4];
                    ldsm4(q, Bs + r * 128 + c * 16);
                    if (ks == 3 && nt2 == 2 && lane == 0)
                        mbar_arrive(sb + 64 + st * 8);   // all reads issued
#pragma unroll
                    for (int mt = 0; mt < 2; mt++) {
                        mma16816(acc[mt][nt2 * 2], a0[mt], q);
                        mma16816(acc[mt][nt2 * 2 + 1], a0[mt], q + 2);
                    }
                }
            }

            // distributed refill: rotating warp issues next stage's loads
            if ((gi & 7) == wid && lane == 0) {
                int f = gi + NST;
                if (f < GI) fill(f);
            }
        }

        // epilogue: registers -> gmem (+bias); stage smem untouched
        int m0 = mb * BM + m_warp;
        int n0 = nb * BN + n_warp;
        float2 bv[6];
#pragma unroll
        for (int nt = 0; nt < 6; nt++)
            bv[nt] = *reinterpret_cast<const float2*>(
                &bias[n0 + nt * 8 + (lane & 3) * 2]);
#pragma unroll
        for (int mt = 0; mt < 2; mt++) {
#pragma unroll
            for (int nt = 0; nt < 6; nt++) {
                int row = m0 + mt * 16 + (lane >> 2);
                int col = n0 + nt * 8 + (lane & 3) * 2;
                float2 v0 = make_float2(acc[mt][nt][0] + bv[nt].x,
                                        acc[mt][nt][1] + bv[nt].y);
                float2 v1 = make_float2(acc[mt][nt][2] + bv[nt].x,
                                        acc[mt][nt][3] + bv[nt].y);
                *reinterpret_cast<float2*>(&C[(size_t)row * N_DIM + col]) = v0;
                *reinterpret_cast<float2*>(&C[(size_t)(row + 8) * N_DIM + col]) = v1;
            }
        }
    }
}

// ---------------------------------------------------------------------------
// Launch
// ---------------------------------------------------------------------------
extern "C" void kernel_launch(void* const* d_in, const int* in_sizes, int n_in,
                              void* d_out, int out_size) {
    const float* A    = (const float*)d_in[0];
    const int*   B    = (const int*)  d_in[1];
    const float* s    = (const float*)d_in[2];
    const float* bias = (const float*)d_in[3];
    float* C = (float*)d_out;

    cudaFuncSetAttribute(gemm_hmma_kernel,
                         cudaFuncAttributeMaxDynamicSharedMemorySize, SMEM_BYTES);

    int nsm = 148;
    cudaDeviceGetAttribute(&nsm, cudaDevAttrMultiProcessorCount, 0);

    convA_kernel<<<(M_DIM * 512) / 256, 256>>>(A);
    dim3 dq_grid(N_DIM / BN, K_DIM / BK);   // 128 x 64 tiles
    dequant_kernel<<<dq_grid, 96>>>(B, s);
    gemm_hmma_kernel<<<nsm, 256, SMEM_BYTES>>>(bias, C);
}

// round 17
// speedup vs baseline: 1.5615x; 1.1237x over previous
#include <cuda_runtime.h>
#include <cuda_fp16.h>
#include <cstdint>

#define M_DIM 4096
#define K_DIM 4096
#define N_DIM 12288

// GEMM tiling: R14 config + superstages (2 kt per sync unit)
constexpr int BM = 128, BN = 192, BK = 64;
constexpr int KT = K_DIM / BK;                 // 64 kt per output tile
constexpr int SSK = KT / 2;                    // 32 superstages per tile
constexpr int NTILES = (M_DIM / BM) * (N_DIM / BN);   // 2048
constexpr int A_TILE = BM * BK * 2;            // 16384 B
constexpr int B_TILE = BN * BK * 2;            // 24576 B
constexpr int SS_BYTES = 2 * (A_TILE + B_TILE);       // 81920 (2 kt)
constexpr int NSS = 2;                         // superstages resident
constexpr int SMEM_OFF = 1024;
constexpr int SMEM_BYTES = SMEM_OFF + NSS * SS_BYTES;  // 164864

// tile-packed, pre-swizzled operand blobs (128B rows, chunk swz c ^ (r&7))
__device__ __half g_Apack[(size_t)M_DIM * K_DIM];   // tiles (mb*64+kt): 128x64
__device__ __half g_Bpack[(size_t)N_DIM * K_DIM];   // tiles (nb*64+kt): 192x64 [n][k]

// ---------------------------------------------------------------------------
// Pack A: fp32 [M,K] -> fp16 swizzled 128x64 tiles
// ---------------------------------------------------------------------------
__global__ void convA_kernel(const float* __restrict__ A) {
    int id = blockIdx.x * 256 + threadIdx.x;    // M*512 16B-chunk ids
    int m = id >> 9;
    int ch = id & 511;
    int kt = ch >> 3, c = ch & 7;
    const float4* src = reinterpret_cast<const float4*>(
        A + (size_t)m * K_DIM + kt * 64 + c * 8);
    float4 v0 = src[0], v1 = src[1];
    __half2 h[4];
    h[0] = __floats2half2_rn(v0.x, v0.y);
    h[1] = __floats2half2_rn(v0.z, v0.w);
    h[2] = __floats2half2_rn(v1.x, v1.y);
    h[3] = __floats2half2_rn(v1.z, v1.w);
    int mb = m >> 7, r = m & 127;
    int cs = c ^ (r & 7);
    char* dst = (char*)g_Apack + (size_t)(mb * 64 + kt) * A_TILE + r * 128 + cs * 16;
    *reinterpret_cast<uint4*>(dst) = *reinterpret_cast<uint4*>(h);
}

// ---------------------------------------------------------------------------
// Dequant+pack W (smem-staged, coalesced): one block per (nb, kt) 192x64 tile.
// ---------------------------------------------------------------------------
__global__ __launch_bounds__(192, 4)
void dequant_kernel(const int* __restrict__ B, const float* __restrict__ s) {
    __shared__ char tile_s[B_TILE];
    int nb = blockIdx.x;            // 0..63
    int kt = blockIdx.y;            // 0..63
    int o_l = threadIdx.x;          // 0..191
    int o = nb * BN + o_l;
    int xm = o_l & 7;
#pragma unroll
    for (int tt = 0; tt < 4; tt++) {
        int t = kt * 4 + tt;
        int2 p = reinterpret_cast<const int2*>(B)[(size_t)t * N_DIM + o];
        float sc = s[(t >> 3) * N_DIM + o];
        __half2 h[8];
#pragma unroll
        for (int c8 = 0; c8 < 2; c8++) {
            int v = c8 ? p.y : p.x;
#pragma unroll
            for (int j = 0; j < 4; j++) {
                float w0 = (float)(((v >> (8 * j)) & 0xF) - 8) * sc;
                float w1 = (float)(((v >> (8 * j + 4)) & 0xF) - 8) * sc;
                h[c8 * 4 + j] = __floats2half2_rn(w0, w1);
            }
        }
        int c0 = tt * 2;
        *reinterpret_cast<uint4*>(tile_s + o_l * 128 + ((c0 ^ xm) * 16)) =
            *reinterpret_cast<uint4*>(h);
        *reinterpret_cast<uint4*>(tile_s + o_l * 128 + (((c0 + 1) ^ xm) * 16)) =
            *reinterpret_cast<uint4*>(h + 4);
    }
    __syncthreads();
    uint4* dst = reinterpret_cast<uint4*>(
        (char*)g_Bpack + (size_t)(nb * 64 + kt) * B_TILE);
    const uint4* srcp = reinterpret_cast<const uint4*>(tile_s);
#pragma unroll
    for (int i = 0; i < B_TILE / 16 / 192; i++)
        dst[i * 192 + threadIdx.x] = srcp[i * 192 + threadIdx.x];
}

// ---------------------------------------------------------------------------
// helpers
// ---------------------------------------------------------------------------
__device__ __forceinline__ uint32_t smem_u32(const void* p) {
    return (uint32_t)__cvta_generic_to_shared(p);
}
__device__ __forceinline__ void mbar_init(uint32_t a, uint32_t cnt) {
    asm volatile("mbarrier.init.shared.b64 [%0], %1;" :: "r"(a), "r"(cnt) : "memory");
}
__device__ __forceinline__ void mbar_expect_tx(uint32_t a, uint32_t bytes) {
    asm volatile("mbarrier.arrive.expect_tx.shared.b64 _, [%0], %1;"
                 :: "r"(a), "r"(bytes) : "memory");
}
__device__ __forceinline__ void mbar_arrive(uint32_t a) {
    asm volatile("mbarrier.arrive.shared.b64 _, [%0];" :: "r"(a) : "memory");
}
__device__ __forceinline__ void mbar_wait(uint32_t a, uint32_t parity) {
    asm volatile(
        "{\n\t.reg .pred P;\n"
        "W0_%=:\n\t"
        "mbarrier.try_wait.parity.acquire.cta.shared::cta.b64 P, [%0], %1, 0x989680;\n\t"
        "@P bra.uni W1_%=;\n\t"
        "bra.uni W0_%=;\n\t"
        "W1_%=:\n\t}"
        :: "r"(a), "r"(parity) : "memory");
}
__device__ __forceinline__ void bulk_g2s(uint32_t dst, const void* src,
                                         uint32_t bytes, uint32_t mbar) {
    asm volatile(
        "cp.async.bulk.shared::cluster.global.mbarrier::complete_tx::bytes "
        "[%0], [%1], %2, [%3];"
        :: "r"(dst), "l"(src), "r"(bytes), "r"(mbar) : "memory");
}
__device__ __forceinline__ void ldsm4(uint32_t* r, uint32_t addr) {
    asm volatile("ldmatrix.sync.aligned.m8n8.x4.shared.b16 {%0,%1,%2,%3}, [%4];"
                 : "=r"(r[0]), "=r"(r[1]), "=r"(r[2]), "=r"(r[3]) : "r"(addr));
}
__device__ __forceinline__ void mma16816(float* c, const uint32_t* a, const uint32_t* b) {
    asm volatile("mma.sync.aligned.m16n8k16.row.col.f32.f16.f16.f32 "
                 "{%0,%1,%2,%3}, {%4,%5,%6,%7}, {%8,%9}, {%0,%1,%2,%3};"
                 : "+f"(c[0]), "+f"(c[1]), "+f"(c[2]), "+f"(c[3])
                 : "r"(a[0]), "r"(a[1]), "r"(a[2]), "r"(a[3]),
                   "r"(b[0]), "r"(b[1]));
}

// ---------------------------------------------------------------------------
// Persistent GEMM. 256 threads = 8 warps (64x48). Superstage pipeline:
// 2 kt per sync unit, 2 superstages resident. One full-wait + one
// empty-arrive + one refill per 2 kt. Distributed refill (rotating warp).
// Superstage slot layout: [A(kt) A(kt+1) B(kt) B(kt+1)].
// ---------------------------------------------------------------------------
__global__ __launch_bounds__(256, 1)
void gemm_hmma_kernel(const float* __restrict__ bias, float* __restrict__ C) {
    extern __shared__ char smem[];
    uint32_t sb = smem_u32(smem);
    int tid = threadIdx.x, wid = tid >> 5, lane = tid & 31;
    int p = blockIdx.x, P = gridDim.x;

    if (tid == 0) {
#pragma unroll
        for (int ss = 0; ss < NSS; ss++) {
            mbar_init(sb + ss * 8, 1);            // full[ss]
            mbar_init(sb + 64 + ss * 8, 8);       // empty[ss]
        }
    }
    __syncthreads();

    int ntiles = (NTILES - p + P - 1) / P;
    int GI = ntiles * SSK;                        // superstage count

    // fill superstage f: A 2-tile (32KB) + B 2-tile (48KB), contiguous in blobs
    auto fill = [&](int f) {
        int ss = f & 1;
        if (f >= NSS) mbar_wait(sb + 64 + ss * 8, ((f >> 1) - 1) & 1);
        int tile = p + (f >> 5) * P;
        int ktf = (f & 31) * 2;
        int mbf = tile & 31, nbf = tile >> 5;
        uint32_t fb = sb + ss * 8;
        mbar_expect_tx(fb, SS_BYTES);
        uint32_t sdst = sb + SMEM_OFF + ss * SS_BYTES;
        bulk_g2s(sdst, (const char*)g_Apack + (size_t)(mbf * 64 + ktf) * A_TILE,
                 2 * A_TILE, fb);
        bulk_g2s(sdst + 2 * A_TILE,
                 (const char*)g_Bpack + (size_t)(nbf * 64 + ktf) * B_TILE,
                 2 * B_TILE, fb);
    };
    if (tid == 0) {
        for (int f = 0; f < NSS && f < GI; f++) fill(f);
    }

    // per-thread ldmatrix geometry (warp tile 64x48, 128B smem rows)
    int g = lane >> 3, tr = lane & 7;
    int m_warp = (wid & 1) * 64;
    int n_warp = (wid >> 1) * 48;
    int aRow0 = m_warp + (g & 1) * 8 + tr;
    int aH = g >> 1;
    int bRow0 = n_warp + (g >> 1) * 8 + tr;
    int bH = g & 1;

    for (int tile_i = 0; tile_i < ntiles; tile_i++) {
        int tile = p + tile_i * P;
        int mb = tile & 31, nb = tile >> 5;

        float acc[4][6][4];
#pragma unroll
        for (int i = 0; i < 4; i++)
#pragma unroll
            for (int j = 0; j < 6; j++)
#pragma unroll
                for (int k = 0; k < 4; k++) acc[i][j][k] = 0.f;

        for (int sk = 0; sk < SSK; sk++) {
            int gsi = tile_i * SSK + sk;
            int ss = gsi & 1;
            mbar_wait(sb + ss * 8, (gsi >> 1) & 1);
            uint32_t base = sb + SMEM_OFF + ss * SS_BYTES;

#pragma unroll
            for (int half = 0; half < 2; half++) {
                uint32_t As = base + half * A_TILE;
                uint32_t Bs = base + 2 * A_TILE + half * B_TILE;
#pragma unroll
                for (int ks = 0; ks < 4; ks++) {
                    int kc = 2 * ks;
                    uint32_t a0[4][4];
#pragma unroll
                    for (int mt = 0; mt < 4; mt++) {
                        int r = aRow0 + mt * 16;
                        int c = (kc + aH) ^ (r & 7);
                        ldsm4(a0[mt], As + r * 128 + c * 16);
                    }
#pragma unroll
                    for (int nt2 = 0; nt2 < 3; nt2++) {
                        int r = bRow0 + nt2 * 16;
                        int c = (kc + bH) ^ (r & 7);
                        uint32_t q[4];
                        ldsm4(q, Bs + r * 128 + c * 16);
                        if (half == 1 && ks == 3 && nt2 == 2 && lane == 0)
                            mbar_arrive(sb + 64 + ss * 8);   // all reads issued
#pragma unroll
                        for (int mt = 0; mt < 4; mt++) {
                            mma16816(acc[mt][nt2 * 2], a0[mt], q);
                            mma16816(acc[mt][nt2 * 2 + 1], a0[mt], q + 2);
                        }
                    }
                }
            }

            // distributed refill: rotating warp issues next superstage's loads
            if ((gsi & 7) == wid && lane == 0) {
                int f = gsi + NSS;
                if (f < GI) fill(f);
            }
        }

        // epilogue: registers -> gmem (+bias); stage smem untouched
        int m0 = mb * BM + m_warp;
        int n0 = nb * BN + n_warp;
        float2 bv[6];
#pragma unroll
        for (int nt = 0; nt < 6; nt++)
            bv[nt] = *reinterpret_cast<const float2*>(
                &bias[n0 + nt * 8 + (lane & 3) * 2]);
#pragma unroll
        for (int mt = 0; mt < 4; mt++) {
#pragma unroll
            for (int nt = 0; nt < 6; nt++) {
                int row = m0 + mt * 16 + (lane >> 2);
                int col = n0 + nt * 8 + (lane & 3) * 2;
                float2 v0 = make_float2(acc[mt][nt][0] + bv[nt].x,
                                        acc[mt][nt][1] + bv[nt].y);
                float2 v1 = make_float2(acc[mt][nt][2] + bv[nt].x,
                                        acc[mt][nt][3] + bv[nt].y);
                *reinterpret_cast<float2*>(&C[(size_t)row * N_DIM + col]) = v0;
                *reinterpret_cast<float2*>(&C[(size_t)(row + 8) * N_DIM + col]) = v1;
            }
        }
    }
}

// ---------------------------------------------------------------------------
// Launch
// ---------------------------------------------------------------------------
extern "C" void kernel_launch(void* const* d_in, const int* in_sizes, int n_in,
                              void* d_out, int out_size) {
    const float* A    = (const float*)d_in[0];
    const int*   B    = (const int*)  d_in[1];
    const float* s    = (const float*)d_in[2];
    const float* bias = (const float*)d_in[3];
    float* C = (float*)d_out;

    cudaFuncSetAttribute(gemm_hmma_kernel,
                         cudaFuncAttributeMaxDynamicSharedMemorySize, SMEM_BYTES);

    int nsm = 148;
    cudaDeviceGetAttribute(&nsm, cudaDevAttrMultiProcessorCount, 0);

    convA_kernel<<<(M_DIM * 512) / 256, 256>>>(A);
    dim3 dq_grid(N_DIM / BN, K_DIM / BK);   // 64 x 64 tiles
    dequant_kernel<<<dq_grid, 192>>>(B, s);
    gemm_hmma_kernel<<<nsm, 256, SMEM_BYTES>>>(bias, C);
}